// round 9
// baseline (speedup 1.0000x reference)
#include <cuda_runtime.h>
#include <cuda_bf16.h>
#include <cstdint>

// Problem constants
#define TT    2048
#define BB    32
#define HHID  512
#define KK    1024          // concat input dim [x|h] or [h1|h2]
#define NPL   64            // CTAs per layer
#define NCTA  128           // total persistent CTAs
#define BH    (BB*HHID)     // 16384 elements per timestep slice
// counters: [L][t][g], g = k-group 0..7, each padded to its own 32B sector
#define CNT_STRIDE 8
#define CNT_PER_L  ((TT + 1) * 8 * CNT_STRIDE)

// ---------------- device global scratch -------------------------------------
__device__ __nv_bfloat16 g_X[(size_t)TT * BH];                 // gathered embeddings
__device__ __nv_bfloat16 g_H[2][(size_t)(TT + 1) * BH];        // h per layer per step
__device__ __nv_bfloat16 g_W[(size_t)NCTA * 32 * KK];          // per-CTA weight slices
__device__ float         g_bias[NCTA * 32];
__device__ int           g_cnt2[2 * CNT_PER_L];                // split counters

// ---------------- helpers ---------------------------------------------------
__device__ __forceinline__ void mma16816(float* c, const uint32_t* a,
                                         uint32_t b0, uint32_t b1) {
    asm volatile(
        "mma.sync.aligned.m16n8k16.row.col.f32.bf16.bf16.f32 "
        "{%0,%1,%2,%3},{%4,%5,%6,%7},{%8,%9},{%0,%1,%2,%3};\n"
        : "+f"(c[0]), "+f"(c[1]), "+f"(c[2]), "+f"(c[3])
        : "r"(a[0]), "r"(a[1]), "r"(a[2]), "r"(a[3]), "r"(b0), "r"(b1));
}

__device__ __forceinline__ float tanh_fast(float x) {
    float y;
    asm("tanh.approx.f32 %0, %1;" : "=f"(y) : "f"(x));
    return y;
}
__device__ __forceinline__ float sig_fast(float x) {
    return fmaf(tanh_fast(0.5f * x), 0.5f, 0.5f);
}

__device__ __forceinline__ int ld_acq(const int* p) {
    int v;
    asm volatile("ld.acquire.gpu.global.s32 %0, [%1];" : "=r"(v) : "l"(p) : "memory");
    return v;
}
__device__ __forceinline__ void red_rel(int* p) {
    asm volatile("red.release.gpu.global.add.s32 [%0], 1;" :: "l"(p) : "memory");
}
// warp-collective wait on ONE split counter (8 producers): lane0 polls
__device__ __forceinline__ void wait_cnt8(const int* p, int lane) {
    int v = 0;
    if (lane == 0) v = ld_acq(p);
    v = __shfl_sync(0xffffffffu, v, 0);
    while (v < 8) {
        __nanosleep(32);
        if (lane == 0) v = ld_acq(p);
        v = __shfl_sync(0xffffffffu, v, 0);
    }
}

// load 32 B-fragment regs (one K=64 slice x N=32) straight from global.
// lane (gid,t4): col = nt*8+gid, elems [k0, k0+1] and [k0+8, k0+9].
__device__ __forceinline__ void ldg_bfrags(uint32_t breg[4][4][2],
                                           const __nv_bfloat16* __restrict__ src,
                                           int gid, int t4, int ks) {
#pragma unroll
    for (int kc = 0; kc < 4; ++kc) {
        int k0 = ks * 64 + kc * 16 + t4 * 2;
#pragma unroll
        for (int nt = 0; nt < 4; ++nt) {
            const __nv_bfloat16* p = src + (nt * 8 + gid) * 512 + k0;
            breg[kc][nt][0] = *(const uint32_t*)p;
            breg[kc][nt][1] = *(const uint32_t*)(p + 8);
        }
    }
}

// ---------------- prep: reorganize weights to per-CTA bf16 slices -----------
__global__ void prep_w_kernel(const float* __restrict__ w_ih,
                              const float* __restrict__ w_hh,
                              const float* __restrict__ b_ih,
                              const float* __restrict__ b_hh) {
    int idx = blockIdx.x * blockDim.x + threadIdx.x;
    if (idx >= NCTA * 32 * KK) return;
    int k   = idx & 1023;
    int r   = (idx >> 10) & 31;
    int cta = idx >> 15;
    int L = cta >> 6, s = cta & 63;
    int g = r >> 3,  j = r & 7;
    int col = g * 512 + s * 8 + j;
    size_t base = ((size_t)L * 2048 + col) * 512;
    float w = (k < 512) ? w_ih[base + k] : w_hh[base + (k - 512)];
    g_W[idx] = __float2bfloat16(w);
    if (k == 0) g_bias[cta * 32 + r] = b_ih[L * 2048 + col] + b_hh[L * 2048 + col];
}

// ---------------- prep: embedding gather to bf16 [t][b][k] ------------------
__global__ void gather_x_kernel(const int* __restrict__ tokens,
                                const float* __restrict__ emb) {
    int idx = blockIdx.x * blockDim.x + threadIdx.x;
    if (idx >= TT * BB * 64) return;
    int k8 = idx & 63;
    int b  = (idx >> 6) & 31;
    int t  = idx >> 11;
    int tok = tokens[b * TT + t];
    const float* e = emb + (size_t)tok * 512 + k8 * 8;
    __nv_bfloat16 v[8];
#pragma unroll
    for (int i = 0; i < 8; ++i) v[i] = __float2bfloat16(e[i]);
    *(uint4*)(g_X + ((size_t)t * BB + b) * 512 + k8 * 8) = *(uint4*)v;
}

// ---------------- prep: init state ------------------------------------------
__global__ void init_kernel() {
    int idx = blockIdx.x * blockDim.x + threadIdx.x;
    if (idx < 2 * CNT_PER_L) {
        int wl = idx % CNT_PER_L;              // within layer
        g_cnt2[idx] = (wl < 8 * CNT_STRIDE && (wl % CNT_STRIDE) == 0) ? 8 : 0;
    }
    if (idx < BH) {
        __nv_bfloat16 z = __float2bfloat16(0.0f);
        g_H[0][idx] = z;
        g_H[1][idx] = z;
    }
}

// ---------------- the persistent LSTM kernel --------------------------------
// 128 CTAs (64/layer), 256 threads. Weights AND activations in registers:
// B-fragments LDG'd directly from global (L1-line-aligned per column slice).
// No SMEM staging at all; SMEM only for the Psum k-reduction.
__global__ void __launch_bounds__(256, 1) lstm_kernel() {
    __shared__ float Psum[8 * 32 * 33];

    const int tid = threadIdx.x;
    const int cta = blockIdx.x;
    const int L = cta >> 6;
    const int s = cta & 63;

    const int ks   = tid >> 5;          // warp = k-slice
    const int lane = tid & 31;
    const int gid  = lane >> 2;
    const int t4   = lane & 3;

    // ---- load weight fragments into registers (once) ----
    const __nv_bfloat16* wsrc = g_W + (size_t)cta * 32 * KK;
    uint32_t areg[2][4][2][4];          // [half][kc][mb][frag]
#pragma unroll
    for (int half = 0; half < 2; ++half)
#pragma unroll
        for (int kc = 0; kc < 4; ++kc) {
            int k0 = half * 512 + ks * 64 + kc * 16 + t4 * 2;
#pragma unroll
            for (int mb = 0; mb < 2; ++mb) {
                int r = mb * 16 + gid;
                areg[half][kc][mb][0] = *(const uint32_t*)(wsrc + r * KK + k0);
                areg[half][kc][mb][1] = *(const uint32_t*)(wsrc + (r + 8) * KK + k0);
                areg[half][kc][mb][2] = *(const uint32_t*)(wsrc + r * KK + k0 + 8);
                areg[half][kc][mb][3] = *(const uint32_t*)(wsrc + (r + 8) * KK + k0 + 8);
            }
        }

    // ---- bias + cell state in registers ----
    const int bact = tid >> 3, jact = tid & 7;      // tid = b*8 + j
    float bias_r[4];
#pragma unroll
    for (int g = 0; g < 4; ++g) bias_r[g] = g_bias[cta * 32 + g * 8 + jact];
    float c_reg = 0.0f;

    int* cnt_own = g_cnt2 + L * CNT_PER_L;
    int* cnt_l0  = g_cnt2;

    uint32_t breg_x[4][4][2];           // x-half B fragments (prefetched)
    uint32_t breg_h[4][4][2];           // h-half B fragments

    // ---- prologue: prefetch x(1) fragments ----
    if (L == 1) wait_cnt8(cnt_l0 + (1 * 8 + ks) * CNT_STRIDE, lane);
    ldg_bfrags(breg_x, (L == 0) ? g_X : (g_H[0] + (size_t)BH), gid, t4, ks);

    for (int t = 1; t <= TT; ++t) {
        float acc[2][4][4];
#pragma unroll
        for (int mb = 0; mb < 2; ++mb)
#pragma unroll
            for (int nt = 0; nt < 4; ++nt)
#pragma unroll
                for (int i = 0; i < 4; ++i) acc[mb][nt][i] = 0.0f;

        // ---- x-half MMA: B already in registers, zero waits ----
#pragma unroll
        for (int kc = 0; kc < 4; ++kc)
#pragma unroll
            for (int nt = 0; nt < 4; ++nt) {
                mma16816(acc[0][nt], areg[0][kc][0], breg_x[kc][nt][0], breg_x[kc][nt][1]);
                mma16816(acc[1][nt], areg[0][kc][1], breg_x[kc][nt][0], breg_x[kc][nt][1]);
            }

        // ---- wait own-layer h(t-1) group counter, LDG h fragments ----
        wait_cnt8(cnt_own + ((t - 1) * 8 + ks) * CNT_STRIDE, lane);
        ldg_bfrags(breg_h, g_H[L] + (size_t)(t - 1) * BH, gid, t4, ks);

        // ---- L0: prefetch x(t+1) fragments now (static data, overlaps h LDG) ----
        if (L == 0 && t < TT)
            ldg_bfrags(breg_x, g_X + (size_t)t * BH, gid, t4, ks);

        // ---- h-half MMA ----
#pragma unroll
        for (int kc = 0; kc < 4; ++kc)
#pragma unroll
            for (int nt = 0; nt < 4; ++nt) {
                mma16816(acc[0][nt], areg[1][kc][0], breg_h[kc][nt][0], breg_h[kc][nt][1]);
                mma16816(acc[1][nt], areg[1][kc][1], breg_h[kc][nt][0], breg_h[kc][nt][1]);
            }

        // ---- write k-partials ----
#pragma unroll
        for (int mb = 0; mb < 2; ++mb)
#pragma unroll
            for (int nt = 0; nt < 4; ++nt) {
                int r = ks * 32 + mb * 16 + gid;
                int c = nt * 8 + t4 * 2;
                Psum[r * 33 + c]           = acc[mb][nt][0];
                Psum[r * 33 + c + 1]       = acc[mb][nt][1];
                Psum[(r + 8) * 33 + c]     = acc[mb][nt][2];
                Psum[(r + 8) * 33 + c + 1] = acc[mb][nt][3];
            }
        __syncthreads();

        // ---- reduce + cell update: thread (b = tid>>3, j = tid&7) ----
        {
            float gv[4];
#pragma unroll
            for (int g = 0; g < 4; ++g) {
                int row = g * 8 + jact;
                float v = bias_r[g];
#pragma unroll
                for (int w = 0; w < 8; ++w) v += Psum[(w * 32 + row) * 33 + bact];
                gv[g] = v;
            }
            float ig = sig_fast(gv[0]);
            float fg = sig_fast(gv[1]);
            float gg = tanh_fast(gv[2]);
            float og = sig_fast(gv[3]);
            c_reg = fg * c_reg + ig * gg;
            float h_new = og * tanh_fast(c_reg);
            g_H[L][(size_t)t * BH + bact * 512 + s * 8 + jact] = __float2bfloat16(h_new);
        }
        __syncthreads();   // all h stores done (also protects Psum reuse)

        // ---- publish: single RED to this CTA's group counter ----
        if (tid == 0) red_rel(cnt_own + (t * 8 + (s >> 3)) * CNT_STRIDE);

        // ---- L1: prefetch x(t+1) fragments after publish (needs h0(t+1)) ----
        if (L == 1 && t < TT) {
            wait_cnt8(cnt_l0 + ((t + 1) * 8 + ks) * CNT_STRIDE, lane);
            ldg_bfrags(breg_x, g_H[0] + (size_t)(t + 1) * BH, gid, t4, ks);
        }
    }
}

// ---------------- final FC + sigmoid ----------------------------------------
__global__ void fc_kernel(const float* __restrict__ fc_w,
                          const float* __restrict__ fc_b,
                          float* __restrict__ out) {
    __shared__ float part[512];
    int tid = threadIdx.x;                 // 512 threads: (b, o, p8)
    int p = tid & 7, o = (tid >> 3) & 1, b = tid >> 4;
    const __nv_bfloat16* h = g_H[1] + (size_t)TT * BH + b * 512 + p * 64;
    const float* w = fc_w + o * 512 + p * 64;
    float sum = 0.0f;
#pragma unroll
    for (int u = 0; u < 64; ++u) sum += __bfloat162float(h[u]) * w[u];
    part[tid] = sum;
    __syncthreads();
    if (p == 0) {
        float v = fc_b[o];
#pragma unroll
        for (int q = 0; q < 8; ++q) v += part[tid + q];
        out[b * 2 + o] = 1.0f / (1.0f + __expf(-v));
    }
}

// ---------------- launch -----------------------------------------------------
extern "C" void kernel_launch(void* const* d_in, const int* in_sizes, int n_in,
                              void* d_out, int out_size) {
    const int*   tokens = (const int*)d_in[0];
    const float* emb    = (const float*)d_in[1];
    const float* w_ih   = (const float*)d_in[2];
    const float* w_hh   = (const float*)d_in[3];
    const float* b_ih   = (const float*)d_in[4];
    const float* b_hh   = (const float*)d_in[5];
    const float* fc_w   = (const float*)d_in[6];
    const float* fc_b   = (const float*)d_in[7];
    float* out = (float*)d_out;

    prep_w_kernel<<<16384, 256>>>(w_ih, w_hh, b_ih, b_hh);
    gather_x_kernel<<<16384, 256>>>(tokens, emb);
    init_kernel<<<(2 * CNT_PER_L + 255) / 256, 256>>>();
    lstm_kernel<<<NCTA, 256>>>();
    fc_kernel<<<1, 512>>>(fc_w, fc_b, out);
}